// round 2
// baseline (speedup 1.0000x reference)
#include <cuda_runtime.h>
#include <math.h>

// Problem constants (fixed by the reference)
#define B_  8
#define L_  1024
#define D_  512
#define V_  64
#define K_  8
#define L2_ 2048            // masks are (B, 2L)
#define INV_TEMP 10.0f
#define EPSF 1e-10f

// -------- deterministic scratch (device globals; no allocations) --------
__device__ float g_den_part[B_ * L_ * 16];   // [b*L+l][t_tile] masked exp partial sums
__device__ float g_cls_S[1024];
__device__ float g_cls_C[1024];
__device__ float g_emp_S[1024];              // [b*128 + chunk]
__device__ float g_emp_C[1024];
__device__ float g_ptr_S[1024];
__device__ float g_ptr_C[1024];
__device__ float g_con_L[2 * B_ * L_];       // [slot][b*L+i]
__device__ float g_con_P[2 * B_ * L_];
__device__ int   g_mask_mode;                // 0=byte bool, 1=int32, 2=float32

// ---- mask dtype probe: attention_mask[:, :L] is guaranteed all-True ----
__global__ void k_detect(const unsigned int* __restrict__ att) {
    unsigned int w = att[0];
    int mode;
    if (w == 1u) mode = 1;                   // int32 {0,1}
    else if (w == 0x3F800000u) mode = 2;     // float32 {0.0,1.0}
    else mode = 0;                           // packed bytes (0x01010101)
    g_mask_mode = mode;
}

__device__ __forceinline__ int mask_at(const void* p, int idx, int mode) {
    if (mode == 1) return ((const int*)p)[idx] != 0;
    if (mode == 2) return ((const float*)p)[idx] != 0.0f;
    return ((const unsigned char*)p)[idx] != 0;
}

// ======================= cls loss =======================
// warp per row (8192 rows of V=64 logits)
__global__ void k_cls(const float* __restrict__ logits, const int* __restrict__ tok) {
    int warp = threadIdx.x >> 5, lane = threadIdx.x & 31;
    int row = blockIdx.x * 8 + warp;
    const float* p = logits + (size_t)row * V_;
    float s0 = p[lane], s1 = p[lane + 32];
    float m = fmaxf(s0, s1);
    #pragma unroll
    for (int o = 16; o; o >>= 1) m = fmaxf(m, __shfl_xor_sync(0xffffffffu, m, o));
    float e = expf(s0 - m) + expf(s1 - m);
    float ss = s0 + s1;
    int t = tok[row];
    float st = (lane == t ? s0 : 0.f) + (lane + 32 == t ? s1 : 0.f);
    #pragma unroll
    for (int o = 16; o; o >>= 1) {
        e  += __shfl_xor_sync(0xffffffffu, e, o);
        ss += __shfl_xor_sync(0xffffffffu, ss, o);
        st += __shfl_xor_sync(0xffffffffu, st, o);
    }
    float lse = m + logf(e);
    float per = 0.9f * (lse - st) + 0.1f * (lse - ss * (1.0f / V_));
    float valid = (t > 3) ? 1.f : 0.f;   // SPECIAL_IDS = 0..3
    __shared__ float sS[8], sC[8];
    if (lane == 0) { sS[warp] = per * valid; sC[warp] = valid; }
    __syncthreads();
    if (threadIdx.x == 0) {
        float a = 0.f, c = 0.f;
        #pragma unroll
        for (int i = 0; i < 8; i++) { a += sS[i]; c += sC[i]; }
        g_cls_S[blockIdx.x] = a; g_cls_C[blockIdx.x] = c;
    }
}

// ======================= empty-pointer BCE =======================
// warp per (b,t); 8192 warps -> 1024 blocks (128 blocks per batch)
__global__ void k_empty(const float* __restrict__ tag, const float* __restrict__ emp,
                        const void* __restrict__ att, const void* __restrict__ dtm) {
    int mode = g_mask_mode;
    int warp = threadIdx.x >> 5, lane = threadIdx.x & 31;
    int gw = blockIdx.x * 8 + warp;
    int b = gw >> 10, t = gw & 1023;
    const float* tp = tag + (size_t)(b * L_ + t) * D_;
    const float* ep = emp + (size_t)b * D_;
    float acc = 0.f;
    #pragma unroll
    for (int i = 0; i < 16; i++) acc += ep[lane + 32 * i] * tp[lane + 32 * i];
    #pragma unroll
    for (int o = 16; o; o >>= 1) acc += __shfl_xor_sync(0xffffffffu, acc, o);
    int a = mask_at(att, b * L2_ + L_ + t, mode);
    int d = mask_at(dtm, b * L2_ + L_ + t, mode);
    float tgt = (a && !d) ? 1.f : 0.f;
    float el = acc;
    float bce = fmaxf(el, 0.f) + log1pf(expf(-fabsf(el))) - el * tgt;  // softplus - el*tgt
    __shared__ float sS[8], sC[8];
    if (lane == 0) { sS[warp] = a ? bce : 0.f; sC[warp] = (float)a; }
    __syncthreads();
    if (threadIdx.x == 0) {
        float s = 0.f, c = 0.f;
        #pragma unroll
        for (int i = 0; i < 8; i++) { s += sS[i]; c += sC[i]; }
        g_emp_S[blockIdx.x] = s; g_emp_C[blockIdx.x] = c;
    }
}

// ======================= fused GEMM + masked exp-sum (den) =======================
// logits[b,l,t] = dot(box[b,l], tag[b,t]) / TEMP ; den[b,l] = sum_{t: dtm} exp(logits)
// 64x64 tile per block, 4x4 micro-tile per thread, never materializes logits.
__global__ void k_gemm(const float* __restrict__ box, const float* __restrict__ tag,
                       const void* __restrict__ dtm) {
    int mode = g_mask_mode;
    int b = blockIdx.z, lt = blockIdx.y, tt = blockIdx.x;
    __shared__ float As[64][33];
    __shared__ float Bs[64][33];
    __shared__ float red[64][17];
    int tid = threadIdx.x, tx = tid & 15, ty = tid >> 4;
    const float* A  = box + (size_t)(b * L_ + lt * 64) * D_;
    const float* Bt = tag + (size_t)(b * L_ + tt * 64) * D_;
    float acc[4][4];
    #pragma unroll
    for (int i = 0; i < 4; i++)
        #pragma unroll
        for (int j = 0; j < 4; j++) acc[i][j] = 0.f;

    for (int kc = 0; kc < D_; kc += 32) {
        #pragma unroll
        for (int u = 0; u < 2; u++) {
            int idx = tid + u * 256;          // 512 float4 = 64 rows x 32 cols
            int r = idx >> 3, c4 = (idx & 7) * 4;
            float4 av = *(const float4*)(A  + (size_t)r * D_ + kc + c4);
            float4 bv = *(const float4*)(Bt + (size_t)r * D_ + kc + c4);
            As[r][c4] = av.x; As[r][c4 + 1] = av.y; As[r][c4 + 2] = av.z; As[r][c4 + 3] = av.w;
            Bs[r][c4] = bv.x; Bs[r][c4 + 1] = bv.y; Bs[r][c4 + 2] = bv.z; Bs[r][c4 + 3] = bv.w;
        }
        __syncthreads();
        #pragma unroll
        for (int k = 0; k < 32; k++) {
            float a[4], bb[4];
            #pragma unroll
            for (int i = 0; i < 4; i++) a[i] = As[ty + 16 * i][k];
            #pragma unroll
            for (int j = 0; j < 4; j++) bb[j] = Bs[tx + 16 * j][k];
            #pragma unroll
            for (int i = 0; i < 4; i++)
                #pragma unroll
                for (int j = 0; j < 4; j++) acc[i][j] += a[i] * bb[j];
        }
        __syncthreads();
    }
    // epilogue: masked exp, reduce over this block's 64 columns
    int tb = tt * 64;
    #pragma unroll
    for (int i = 0; i < 4; i++) {
        float sum = 0.f;
        #pragma unroll
        for (int j = 0; j < 4; j++) {
            int tc = tb + tx + 16 * j;
            if (mask_at(dtm, b * L2_ + L_ + tc, mode)) sum += expf(acc[i][j] * INV_TEMP);
        }
        red[ty + 16 * i][tx] = sum;
    }
    __syncthreads();
    if (tid < 64) {
        float s = 0.f;
        #pragma unroll
        for (int x = 0; x < 16; x++) s += red[tid][x];
        g_den_part[(size_t)(b * L_ + lt * 64 + tid) * 16 + tt] = s;
    }
}

// ======================= pointer loss (targets + combine) =======================
// warp per (b,l): reduce den partials, recompute the K<=8 target dots, accumulate terms
__global__ void k_ptr(const float* __restrict__ box, const float* __restrict__ tag,
                      const int* __restrict__ bidx, const void* __restrict__ dtm) {
    int mode = g_mask_mode;
    int warp = threadIdx.x >> 5, lane = threadIdx.x & 31;
    int gw = blockIdx.x * 8 + warp;          // gw = b*L + l
    int b = gw >> 10;
    float dv = (lane < 16) ? g_den_part[(size_t)gw * 16 + lane] : 0.f;
    #pragma unroll
    for (int o = 16; o; o >>= 1) dv += __shfl_xor_sync(0xffffffffu, dv, o);
    float logden = logf(dv + EPSF);
    const int* bi = bidx + (size_t)gw * K_;
    const float* brow = box + (size_t)gw * D_;
    float ts = 0.f, tc = 0.f;
    bool valid = true;
    for (int k = 0; k < K_; k++) {
        int idx = bi[k];                      // warp-uniform
        if (idx < 0) valid = false;           // cumprod semantics: invalid from here on
        if (valid) {
            int rc = idx - L_;
            rc = rc < 0 ? 0 : (rc > L_ - 1 ? L_ - 1 : rc);
            if (mask_at(dtm, b * L2_ + L_ + rc, mode)) {
                const float* trow = tag + (size_t)(b * L_ + rc) * D_;
                float a = 0.f;
                #pragma unroll
                for (int i = 0; i < 16; i++) a += brow[lane + 32 * i] * trow[lane + 32 * i];
                #pragma unroll
                for (int o = 16; o; o >>= 1) a += __shfl_xor_sync(0xffffffffu, a, o);
                ts += logden - a * INV_TEMP;
                tc += 1.f;
            }
        }
    }
    __shared__ float sS[8], sC[8];
    if (lane == 0) { sS[warp] = ts; sC[warp] = tc; }
    __syncthreads();
    if (threadIdx.x == 0) {
        float s = 0.f, c = 0.f;
        #pragma unroll
        for (int i = 0; i < 8; i++) { s += sS[i]; c += sC[i]; }
        g_ptr_S[blockIdx.x] = s; g_ptr_C[blockIdx.x] = c;
    }
}

// ======================= span contrastive =======================
// block per (b,i) row: 1024 sim + 1024 coef held in registers (4 each / thread)
__global__ void k_contr(const float* __restrict__ sim, const float* __restrict__ coef, int slot) {
    int bi = blockIdx.x;
    int i = bi & 1023;
    int tid = threadIdx.x;
    const float4 sv = *(const float4*)(sim  + (size_t)bi * L_ + tid * 4);
    const float4 cv = *(const float4*)(coef + (size_t)bi * L_ + tid * 4);
    float s[4] = { sv.x * INV_TEMP, sv.y * INV_TEMP, sv.z * INV_TEMP, sv.w * INV_TEMP };
    float c[4] = { cv.x, cv.y, cv.z, cv.w };
    float m = fmaxf(fmaxf(s[0], s[1]), fmaxf(s[2], s[3]));
    #pragma unroll
    for (int o = 16; o; o >>= 1) m = fmaxf(m, __shfl_xor_sync(0xffffffffu, m, o));
    __shared__ float smax[8];
    __shared__ float sacc[8][3];
    __shared__ float sdiag;
    if ((tid & 31) == 0) smax[tid >> 5] = m;
    __syncthreads();
    if (tid == 0) {
        float mm = smax[0];
        #pragma unroll
        for (int w = 1; w < 8; w++) mm = fmaxf(mm, smax[w]);
        smax[0] = mm;
    }
    __syncthreads();
    m = smax[0];
    float es = 0.f, W = 0.f, WS = 0.f;
    #pragma unroll
    for (int q = 0; q < 4; q++) {
        float sq = s[q] - m;
        float e = expf(sq);
        es += e;
        if (tid * 4 + q == i) sdiag = e;      // exactly one thread per block
        float w = c[q] > 0.f ? c[q] : 0.f;
        W += w; WS += w * sq;
    }
    #pragma unroll
    for (int o = 16; o; o >>= 1) {
        es += __shfl_xor_sync(0xffffffffu, es, o);
        W  += __shfl_xor_sync(0xffffffffu, W, o);
        WS += __shfl_xor_sync(0xffffffffu, WS, o);
    }
    if ((tid & 31) == 0) { sacc[tid >> 5][0] = es; sacc[tid >> 5][1] = W; sacc[tid >> 5][2] = WS; }
    __syncthreads();
    if (tid == 0) {
        float E = 0.f, Wt = 0.f, WSt = 0.f;
        #pragma unroll
        for (int w = 0; w < 8; w++) { E += sacc[w][0]; Wt += sacc[w][1]; WSt += sacc[w][2]; }
        float den = E - sdiag;
        float logden = logf(den + EPSF);
        float haspos = Wt > 0.f ? 1.f : 0.f;
        float loss = (logden * Wt - WSt) / (Wt + EPSF);
        g_con_L[slot * (B_ * L_) + bi] = haspos * loss;
        g_con_P[slot * (B_ * L_) + bi] = haspos;
    }
}

// ======================= final deterministic combine =======================
__device__ float blk_sum(const float* p, int n, volatile float* sh) {
    float a = 0.f;
    for (int i = threadIdx.x; i < n; i += 256) a += p[i];
    #pragma unroll
    for (int o = 16; o; o >>= 1) a += __shfl_xor_sync(0xffffffffu, a, o);
    __syncthreads();
    if ((threadIdx.x & 31) == 0) sh[threadIdx.x >> 5] = a;
    __syncthreads();
    if (threadIdx.x == 0) {
        float r = 0.f;
        for (int w = 0; w < 8; w++) r += sh[w];
        sh[8] = r;
    }
    __syncthreads();
    float r = sh[8];
    __syncthreads();
    return r;
}

__global__ void k_final(float* __restrict__ out) {
    __shared__ float sh[16];
    float clsS = blk_sum(g_cls_S, 1024, sh);
    float clsC = blk_sum(g_cls_C, 1024, sh);
    float cls = clsS / fmaxf(clsC, 1.f);

    float emp = 0.f;
    for (int b = 0; b < B_; b++) {
        float S = blk_sum(g_emp_S + b * 128, 128, sh);
        float C = blk_sum(g_emp_C + b * 128, 128, sh);
        emp += S / fmaxf(C, 1.f);
    }
    emp *= (1.f / B_);

    float ptrS = blk_sum(g_ptr_S, 1024, sh);
    float ptrC = blk_sum(g_ptr_C, 1024, sh);
    float ptr = (ptrC > 0.f) ? ptrS / fmaxf(ptrC, 1.f) : 0.f;

    float rL = blk_sum(g_con_L, B_ * L_, sh);
    float rP = blk_sum(g_con_P, B_ * L_, sh);
    float row = (rP > 0.f) ? rL / fmaxf(rP, 1.f) : 0.f;

    float cL = blk_sum(g_con_L + B_ * L_, B_ * L_, sh);
    float cP = blk_sum(g_con_P + B_ * L_, B_ * L_, sh);
    float col = (cP > 0.f) ? cL / fmaxf(cP, 1.f) : 0.f;

    if (threadIdx.x == 0) {
        out[1] = cls; out[2] = ptr; out[3] = emp; out[4] = row; out[5] = col;
        out[0] = cls + ptr + emp + 0.5f * row + 0.5f * col;
    }
}

// ======================= launch =======================
extern "C" void kernel_launch(void* const* d_in, const int* in_sizes, int n_in,
                              void* d_out, int out_size) {
    (void)in_sizes; (void)n_in; (void)out_size;
    const int*           tok  = (const int*)d_in[0];            // token_ids (B,L)
    const int*           bidx = (const int*)d_in[1];            // box_indices (B,L,K)
    const void*          dtm  = d_in[2];                        // data_tag_mask (B,2L)
    const void*          att  = d_in[3];                        // attention_mask (B,2L)
    const float*         tlog = (const float*)d_in[4];          // tag_logits (B,L,V)
    const float*         boxp = (const float*)d_in[5];          // box_proj (B,L,D)
    const float*         tagp = (const float*)d_in[6];          // tag_proj (B,L,D)
    const float*         empp = (const float*)d_in[7];          // empty_proj (B,1,D)
    const float*         rsim = (const float*)d_in[8];
    const float*         csim = (const float*)d_in[9];
    const float*         rco  = (const float*)d_in[10];
    const float*         cco  = (const float*)d_in[11];
    float* out = (float*)d_out;

    k_detect<<<1, 1>>>((const unsigned int*)att);
    k_cls<<<1024, 256>>>(tlog, tok);
    k_empty<<<1024, 256>>>(tagp, empp, att, dtm);
    dim3 gg(16, 16, B_);
    k_gemm<<<gg, 256>>>(boxp, tagp, dtm);
    k_ptr<<<1024, 256>>>(boxp, tagp, bidx, dtm);
    k_contr<<<B_ * L_, 256>>>(rsim, rco, 0);
    k_contr<<<B_ * L_, 256>>>(csim, cco, 1);
    k_final<<<1, 256>>>(out);
}

// round 6
// speedup vs baseline: 1.3698x; 1.3698x over previous
#include <cuda_runtime.h>
#include <math.h>
#include <stdint.h>
#include <mma.h>

using namespace nvcuda;

// Problem constants (fixed by the reference)
#define B_  8
#define L_  1024
#define D_  512
#define V_  64
#define K_  8
#define L2_ 2048            // masks are (B, 2L)
#define INV_TEMP 10.0f
#define EPSF 1e-10f

// -------- deterministic scratch (device globals; no allocations) --------
__device__ float g_den_part[B_ * L_ * 8];    // [b*L+l][t_tile(128-wide)] masked exp partial sums
__device__ float g_cls_S[1024];
__device__ float g_cls_C[1024];
__device__ float g_emp_S[1024];              // [b*128 + chunk]
__device__ float g_emp_C[1024];
__device__ float g_ptr_S[1024];
__device__ float g_ptr_C[1024];
__device__ float g_con_L[2 * B_ * L_];       // [slot][b*L+i]
__device__ float g_con_P[2 * B_ * L_];
__device__ int   g_mask_mode;                // 0=byte bool, 1=int32, 2=float32

// ---- mask dtype probe: attention_mask[:, :L] is guaranteed all-True ----
__global__ void k_detect(const unsigned int* __restrict__ att) {
    unsigned int w = att[0];
    int mode;
    if (w == 1u) mode = 1;                   // int32 {0,1}
    else if (w == 0x3F800000u) mode = 2;     // float32 {0.0,1.0}
    else mode = 0;                           // packed bytes (0x01010101)
    g_mask_mode = mode;
}

__device__ __forceinline__ int mask_at(const void* p, int idx, int mode) {
    if (mode == 1) return ((const int*)p)[idx] != 0;
    if (mode == 2) return ((const float*)p)[idx] != 0.0f;
    return ((const unsigned char*)p)[idx] != 0;
}

// ======================= cls loss =======================
__global__ void __launch_bounds__(256) k_cls(const float* __restrict__ logits,
                                             const int* __restrict__ tok) {
    int warp = threadIdx.x >> 5, lane = threadIdx.x & 31;
    int row = blockIdx.x * 8 + warp;
    const float* p = logits + (size_t)row * V_;
    float s0 = p[lane], s1 = p[lane + 32];
    float m = fmaxf(s0, s1);
    #pragma unroll
    for (int o = 16; o; o >>= 1) m = fmaxf(m, __shfl_xor_sync(0xffffffffu, m, o));
    float e = expf(s0 - m) + expf(s1 - m);
    float ss = s0 + s1;
    int t = tok[row];
    float st = (lane == t ? s0 : 0.f) + (lane + 32 == t ? s1 : 0.f);
    #pragma unroll
    for (int o = 16; o; o >>= 1) {
        e  += __shfl_xor_sync(0xffffffffu, e, o);
        ss += __shfl_xor_sync(0xffffffffu, ss, o);
        st += __shfl_xor_sync(0xffffffffu, st, o);
    }
    float lse = m + logf(e);
    float per = 0.9f * (lse - st) + 0.1f * (lse - ss * (1.0f / V_));
    float valid = (t > 3) ? 1.f : 0.f;   // SPECIAL_IDS = 0..3
    __shared__ float sS[8], sC[8];
    if (lane == 0) { sS[warp] = per * valid; sC[warp] = valid; }
    __syncthreads();
    if (threadIdx.x == 0) {
        float a = 0.f, c = 0.f;
        #pragma unroll
        for (int i = 0; i < 8; i++) { a += sS[i]; c += sC[i]; }
        g_cls_S[blockIdx.x] = a; g_cls_C[blockIdx.x] = c;
    }
}

// ======================= empty-pointer BCE =======================
__global__ void __launch_bounds__(256) k_empty(const float* __restrict__ tag,
                                               const float* __restrict__ emp,
                                               const void* __restrict__ att,
                                               const void* __restrict__ dtm) {
    int mode = g_mask_mode;
    int warp = threadIdx.x >> 5, lane = threadIdx.x & 31;
    int gw = blockIdx.x * 8 + warp;
    int b = gw >> 10, t = gw & 1023;
    const float* tp = tag + (size_t)(b * L_ + t) * D_;
    const float* ep = emp + (size_t)b * D_;
    float acc = 0.f;
    #pragma unroll
    for (int i = 0; i < 16; i++) acc += ep[lane + 32 * i] * tp[lane + 32 * i];
    #pragma unroll
    for (int o = 16; o; o >>= 1) acc += __shfl_xor_sync(0xffffffffu, acc, o);
    int a = mask_at(att, b * L2_ + L_ + t, mode);
    int d = mask_at(dtm, b * L2_ + L_ + t, mode);
    float tgt = (a && !d) ? 1.f : 0.f;
    float el = acc;
    float bce = fmaxf(el, 0.f) + log1pf(expf(-fabsf(el))) - el * tgt;
    __shared__ float sS[8], sC[8];
    if (lane == 0) { sS[warp] = a ? bce : 0.f; sC[warp] = (float)a; }
    __syncthreads();
    if (threadIdx.x == 0) {
        float s = 0.f, c = 0.f;
        #pragma unroll
        for (int i = 0; i < 8; i++) { s += sS[i]; c += sC[i]; }
        g_emp_S[blockIdx.x] = s; g_emp_C[blockIdx.x] = c;
    }
}

// ======================= wmma tf32 GEMM + masked exp-sum =======================
// 128x128 tile per block; 8 warps in 4x2; warp tile 32x64 as 2x4 m16n16k8 frags.
// den[b,l] partial over this block's 128 t-columns -> g_den_part[row][tt]
__global__ void __launch_bounds__(256, 1) k_gemm(const float* __restrict__ box,
                                                 const float* __restrict__ tag,
                                                 const void* __restrict__ dtm) {
    __shared__ float As[128][36];                     // tf32-rounded floats, stride 36
    __shared__ float Bs[128][36];
    __shared__ alignas(32) float scratch[8][16][20];  // per-warp staging; ldm=20 (mult of 4), 32B-aligned slices
    __shared__ float red[128][2];
    __shared__ unsigned char sdtm[128];

    int mode = g_mask_mode;
    int b = blockIdx.z, lt = blockIdx.y, tt = blockIdx.x;
    int tid = threadIdx.x;
    int wid = tid >> 5, lane = tid & 31;
    int wm = wid >> 1, wn = wid & 1;     // 4 x 2 warp grid

    if (tid < 128) sdtm[tid] = (unsigned char)mask_at(dtm, b * L2_ + L_ + tt * 128 + tid, mode);

    const float* A  = box + (size_t)(b * L_ + lt * 128) * D_;
    const float* Bt = tag + (size_t)(b * L_ + tt * 128) * D_;

    wmma::fragment<wmma::accumulator, 16, 16, 8, float> acc[2][4];
    #pragma unroll
    for (int mi = 0; mi < 2; mi++)
        #pragma unroll
        for (int ni = 0; ni < 4; ni++)
            wmma::fill_fragment(acc[mi][ni], 0.0f);

    for (int kc = 0; kc < D_; kc += 32) {
        #pragma unroll
        for (int it = 0; it < 4; it++) {
            int idx = tid + it * 256;            // 0..1023 : 128 rows x 8 float4
            int r = idx >> 3, c4 = (idx & 7) * 4;
            float4 av = *(const float4*)(A  + (size_t)r * D_ + kc + c4);
            float4 bv = *(const float4*)(Bt + (size_t)r * D_ + kc + c4);
            As[r][c4]     = wmma::__float_to_tf32(av.x);
            As[r][c4 + 1] = wmma::__float_to_tf32(av.y);
            As[r][c4 + 2] = wmma::__float_to_tf32(av.z);
            As[r][c4 + 3] = wmma::__float_to_tf32(av.w);
            Bs[r][c4]     = wmma::__float_to_tf32(bv.x);
            Bs[r][c4 + 1] = wmma::__float_to_tf32(bv.y);
            Bs[r][c4 + 2] = wmma::__float_to_tf32(bv.z);
            Bs[r][c4 + 3] = wmma::__float_to_tf32(bv.w);
        }
        __syncthreads();
        #pragma unroll
        for (int kk = 0; kk < 32; kk += 8) {
            wmma::fragment<wmma::matrix_a, 16, 16, 8, wmma::precision::tf32, wmma::row_major> af[2];
            #pragma unroll
            for (int mi = 0; mi < 2; mi++)
                wmma::load_matrix_sync(af[mi], &As[wm * 32 + mi * 16][kk], 36);
            wmma::fragment<wmma::matrix_b, 16, 16, 8, wmma::precision::tf32, wmma::col_major> bf[4];
            #pragma unroll
            for (int ni = 0; ni < 4; ni++)
                wmma::load_matrix_sync(bf[ni], &Bs[wn * 64 + ni * 16][kk], 36);
            #pragma unroll
            for (int mi = 0; mi < 2; mi++)
                #pragma unroll
                for (int ni = 0; ni < 4; ni++)
                    wmma::mma_sync(acc[mi][ni], af[mi], bf[ni], acc[mi][ni]);
        }
        __syncthreads();
    }

    // epilogue: masked exp + row reduce via per-warp smem staging
    int r = lane & 15, h = lane >> 4;    // row within frag, column half
    #pragma unroll
    for (int mi = 0; mi < 2; mi++) {
        float rowsum = 0.f;
        #pragma unroll
        for (int ni = 0; ni < 4; ni++) {
            wmma::store_matrix_sync(&scratch[wid][0][0], acc[mi][ni], 20, wmma::mem_row_major);
            __syncwarp();
            float s = 0.f;
            #pragma unroll
            for (int c = 0; c < 8; c++) {
                int col = h * 8 + c;
                int gc = wn * 64 + ni * 16 + col;
                if (sdtm[gc]) s += __expf(scratch[wid][r][col] * INV_TEMP);
            }
            rowsum += s;
            __syncwarp();
        }
        rowsum += __shfl_xor_sync(0xffffffffu, rowsum, 16);
        if (h == 0) red[wm * 32 + mi * 16 + r][wn] = rowsum;
    }
    __syncthreads();
    if (tid < 128) {
        float s = red[tid][0] + red[tid][1];
        g_den_part[(size_t)(b * L_ + lt * 128 + tid) * 8 + tt] = s;
    }
}

// ======================= pointer loss (targets + combine) =======================
__global__ void __launch_bounds__(256) k_ptr(const float* __restrict__ box,
                                             const float* __restrict__ tag,
                                             const int* __restrict__ bidx,
                                             const void* __restrict__ dtm) {
    int mode = g_mask_mode;
    int warp = threadIdx.x >> 5, lane = threadIdx.x & 31;
    int gw = blockIdx.x * 8 + warp;          // gw = b*L + l
    int b = gw >> 10;
    float dv = (lane < 8) ? g_den_part[(size_t)gw * 8 + lane] : 0.f;
    #pragma unroll
    for (int o = 16; o; o >>= 1) dv += __shfl_xor_sync(0xffffffffu, dv, o);
    float logden = logf(dv + EPSF);
    const int* bi = bidx + (size_t)gw * K_;
    const float* brow = box + (size_t)gw * D_;
    float ts = 0.f, tc = 0.f;
    bool valid = true;
    for (int k = 0; k < K_; k++) {
        int idx = bi[k];
        if (idx < 0) valid = false;
        if (valid) {
            int rc = idx - L_;
            rc = rc < 0 ? 0 : (rc > L_ - 1 ? L_ - 1 : rc);
            if (mask_at(dtm, b * L2_ + L_ + rc, mode)) {
                const float* trow = tag + (size_t)(b * L_ + rc) * D_;
                float a = 0.f;
                #pragma unroll
                for (int i = 0; i < 16; i++) a += brow[lane + 32 * i] * trow[lane + 32 * i];
                #pragma unroll
                for (int o = 16; o; o >>= 1) a += __shfl_xor_sync(0xffffffffu, a, o);
                ts += logden - a * INV_TEMP;
                tc += 1.f;
            }
        }
    }
    __shared__ float sS[8], sC[8];
    if (lane == 0) { sS[warp] = ts; sC[warp] = tc; }
    __syncthreads();
    if (threadIdx.x == 0) {
        float s = 0.f, c = 0.f;
        #pragma unroll
        for (int i = 0; i < 8; i++) { s += sS[i]; c += sC[i]; }
        g_ptr_S[blockIdx.x] = s; g_ptr_C[blockIdx.x] = c;
    }
}

// ======================= span contrastive =======================
__global__ void __launch_bounds__(256) k_contr(const float* __restrict__ sim,
                                               const float* __restrict__ coef, int slot) {
    int bi = blockIdx.x;
    int i = bi & 1023;
    int tid = threadIdx.x;
    const float4 sv = *(const float4*)(sim  + (size_t)bi * L_ + tid * 4);
    const float4 cv = *(const float4*)(coef + (size_t)bi * L_ + tid * 4);
    float s[4] = { sv.x * INV_TEMP, sv.y * INV_TEMP, sv.z * INV_TEMP, sv.w * INV_TEMP };
    float c[4] = { cv.x, cv.y, cv.z, cv.w };
    float m = fmaxf(fmaxf(s[0], s[1]), fmaxf(s[2], s[3]));
    #pragma unroll
    for (int o = 16; o; o >>= 1) m = fmaxf(m, __shfl_xor_sync(0xffffffffu, m, o));
    __shared__ float smax[8];
    __shared__ float sacc[8][3];
    __shared__ float sdiag;
    if ((tid & 31) == 0) smax[tid >> 5] = m;
    __syncthreads();
    if (tid == 0) {
        float mm = smax[0];
        #pragma unroll
        for (int w = 1; w < 8; w++) mm = fmaxf(mm, smax[w]);
        smax[0] = mm;
    }
    __syncthreads();
    m = smax[0];
    float es = 0.f, W = 0.f, WS = 0.f;
    #pragma unroll
    for (int q = 0; q < 4; q++) {
        float sq = s[q] - m;
        float e = expf(sq);
        es += e;
        if (tid * 4 + q == i) sdiag = e;
        float w = c[q] > 0.f ? c[q] : 0.f;
        W += w; WS += w * sq;
    }
    #pragma unroll
    for (int o = 16; o; o >>= 1) {
        es += __shfl_xor_sync(0xffffffffu, es, o);
        W  += __shfl_xor_sync(0xffffffffu, W, o);
        WS += __shfl_xor_sync(0xffffffffu, WS, o);
    }
    if ((tid & 31) == 0) { sacc[tid >> 5][0] = es; sacc[tid >> 5][1] = W; sacc[tid >> 5][2] = WS; }
    __syncthreads();
    if (tid == 0) {
        float E = 0.f, Wt = 0.f, WSt = 0.f;
        #pragma unroll
        for (int w = 0; w < 8; w++) { E += sacc[w][0]; Wt += sacc[w][1]; WSt += sacc[w][2]; }
        float den = E - sdiag;
        float logden = logf(den + EPSF);
        float haspos = Wt > 0.f ? 1.f : 0.f;
        float loss = (logden * Wt - WSt) / (Wt + EPSF);
        g_con_L[slot * (B_ * L_) + bi] = haspos * loss;
        g_con_P[slot * (B_ * L_) + bi] = haspos;
    }
}

// ======================= final deterministic combine =======================
__device__ float blk_sum(const float* p, int n, volatile float* sh) {
    float a = 0.f;
    for (int i = threadIdx.x; i < n; i += 256) a += p[i];
    #pragma unroll
    for (int o = 16; o; o >>= 1) a += __shfl_xor_sync(0xffffffffu, a, o);
    __syncthreads();
    if ((threadIdx.x & 31) == 0) sh[threadIdx.x >> 5] = a;
    __syncthreads();
    if (threadIdx.x == 0) {
        float r = 0.f;
        for (int w = 0; w < 8; w++) r += sh[w];
        sh[8] = r;
    }
    __syncthreads();
    float r = sh[8];
    __syncthreads();
    return r;
}

__global__ void __launch_bounds__(256) k_final(float* __restrict__ out) {
    __shared__ float sh[16];
    float clsS = blk_sum(g_cls_S, 1024, sh);
    float clsC = blk_sum(g_cls_C, 1024, sh);
    float cls = clsS / fmaxf(clsC, 1.f);

    float emp = 0.f;
    for (int b = 0; b < B_; b++) {
        float S = blk_sum(g_emp_S + b * 128, 128, sh);
        float C = blk_sum(g_emp_C + b * 128, 128, sh);
        emp += S / fmaxf(C, 1.f);
    }
    emp *= (1.f / B_);

    float ptrS = blk_sum(g_ptr_S, 1024, sh);
    float ptrC = blk_sum(g_ptr_C, 1024, sh);
    float ptr = (ptrC > 0.f) ? ptrS / fmaxf(ptrC, 1.f) : 0.f;

    float rL = blk_sum(g_con_L, B_ * L_, sh);
    float rP = blk_sum(g_con_P, B_ * L_, sh);
    float row = (rP > 0.f) ? rL / fmaxf(rP, 1.f) : 0.f;

    float cL = blk_sum(g_con_L + B_ * L_, B_ * L_, sh);
    float cP = blk_sum(g_con_P + B_ * L_, B_ * L_, sh);
    float col = (cP > 0.f) ? cL / fmaxf(cP, 1.f) : 0.f;

    if (threadIdx.x == 0) {
        out[1] = cls; out[2] = ptr; out[3] = emp; out[4] = row; out[5] = col;
        out[0] = cls + ptr + emp + 0.5f * row + 0.5f * col;
    }
}

// ======================= launch =======================
extern "C" void kernel_launch(void* const* d_in, const int* in_sizes, int n_in,
                              void* d_out, int out_size) {
    (void)in_sizes; (void)n_in; (void)out_size;
    const int*           tok  = (const int*)d_in[0];            // token_ids (B,L)
    const int*           bidx = (const int*)d_in[1];            // box_indices (B,L,K)
    const void*          dtm  = d_in[2];                        // data_tag_mask (B,2L)
    const void*          att  = d_in[3];                        // attention_mask (B,2L)
    const float*         tlog = (const float*)d_in[4];          // tag_logits (B,L,V)
    const float*         boxp = (const float*)d_in[5];          // box_proj (B,L,D)
    const float*         tagp = (const float*)d_in[6];          // tag_proj (B,L,D)
    const float*         empp = (const float*)d_in[7];          // empty_proj (B,1,D)
    const float*         rsim = (const float*)d_in[8];
    const float*         csim = (const float*)d_in[9];
    const float*         rco  = (const float*)d_in[10];
    const float*         cco  = (const float*)d_in[11];
    float* out = (float*)d_out;

    k_detect<<<1, 1>>>((const unsigned int*)att);
    k_cls<<<1024, 256>>>(tlog, tok);
    k_empty<<<1024, 256>>>(tagp, empp, att, dtm);
    dim3 gg(8, 8, B_);
    k_gemm<<<gg, 256>>>(boxp, tagp, dtm);
    k_ptr<<<1024, 256>>>(boxp, tagp, bidx, dtm);
    k_contr<<<B_ * L_, 256>>>(rsim, rco, 0);
    k_contr<<<B_ * L_, 256>>>(csim, cco, 1);
    k_final<<<1, 256>>>(out);
}

// round 7
// speedup vs baseline: 1.5572x; 1.1368x over previous
#include <cuda_runtime.h>
#include <cuda_pipeline.h>
#include <math.h>
#include <stdint.h>
#include <mma.h>

using namespace nvcuda;

// Problem constants (fixed by the reference)
#define B_  8
#define L_  1024
#define D_  512
#define V_  64
#define K_  8
#define L2_ 2048            // masks are (B, 2L)
#define INV_TEMP 10.0f
#define EPSF 1e-10f
#define KCH 16              // k-chunk per pipeline stage

// -------- deterministic scratch (device globals; no allocations) --------
__device__ float g_den_part[B_ * L_ * 8];    // [b*L+l][t_tile(128-wide)] masked exp partial sums
__device__ float g_cls_S[1024];
__device__ float g_cls_C[1024];
__device__ float g_emp_S[1024];              // [b*128 + chunk]
__device__ float g_emp_C[1024];
__device__ float g_ptr_S[1024];
__device__ float g_ptr_C[1024];
__device__ float g_con_L[2 * B_ * L_];       // [slot][b*L+i]
__device__ float g_con_P[2 * B_ * L_];
__device__ int   g_mask_mode;                // 0=byte bool, 1=int32, 2=float32

// ---- mask dtype probe: attention_mask[:, :L] is guaranteed all-True ----
__global__ void k_detect(const unsigned int* __restrict__ att) {
    unsigned int w = att[0];
    int mode;
    if (w == 1u) mode = 1;                   // int32 {0,1}
    else if (w == 0x3F800000u) mode = 2;     // float32 {0.0,1.0}
    else mode = 0;                           // packed bytes (0x01010101)
    g_mask_mode = mode;
}

__device__ __forceinline__ int mask_at(const void* p, int idx, int mode) {
    if (mode == 1) return ((const int*)p)[idx] != 0;
    if (mode == 2) return ((const float*)p)[idx] != 0.0f;
    return ((const unsigned char*)p)[idx] != 0;
}

// ======================= cls loss =======================
__global__ void __launch_bounds__(256) k_cls(const float* __restrict__ logits,
                                             const int* __restrict__ tok) {
    int warp = threadIdx.x >> 5, lane = threadIdx.x & 31;
    int row = blockIdx.x * 8 + warp;
    const float* p = logits + (size_t)row * V_;
    float s0 = p[lane], s1 = p[lane + 32];
    float m = fmaxf(s0, s1);
    #pragma unroll
    for (int o = 16; o; o >>= 1) m = fmaxf(m, __shfl_xor_sync(0xffffffffu, m, o));
    float e = expf(s0 - m) + expf(s1 - m);
    float ss = s0 + s1;
    int t = tok[row];
    float st = (lane == t ? s0 : 0.f) + (lane + 32 == t ? s1 : 0.f);
    #pragma unroll
    for (int o = 16; o; o >>= 1) {
        e  += __shfl_xor_sync(0xffffffffu, e, o);
        ss += __shfl_xor_sync(0xffffffffu, ss, o);
        st += __shfl_xor_sync(0xffffffffu, st, o);
    }
    float lse = m + logf(e);
    float per = 0.9f * (lse - st) + 0.1f * (lse - ss * (1.0f / V_));
    float valid = (t > 3) ? 1.f : 0.f;   // SPECIAL_IDS = 0..3
    __shared__ float sS[8], sC[8];
    if (lane == 0) { sS[warp] = per * valid; sC[warp] = valid; }
    __syncthreads();
    if (threadIdx.x == 0) {
        float a = 0.f, c = 0.f;
        #pragma unroll
        for (int i = 0; i < 8; i++) { a += sS[i]; c += sC[i]; }
        g_cls_S[blockIdx.x] = a; g_cls_C[blockIdx.x] = c;
    }
}

// ======================= empty-pointer BCE =======================
__global__ void __launch_bounds__(256) k_empty(const float* __restrict__ tag,
                                               const float* __restrict__ emp,
                                               const void* __restrict__ att,
                                               const void* __restrict__ dtm) {
    int mode = g_mask_mode;
    int warp = threadIdx.x >> 5, lane = threadIdx.x & 31;
    int gw = blockIdx.x * 8 + warp;
    int b = gw >> 10, t = gw & 1023;
    const float* tp = tag + (size_t)(b * L_ + t) * D_;
    const float* ep = emp + (size_t)b * D_;
    float acc = 0.f;
    #pragma unroll
    for (int i = 0; i < 16; i++) acc += ep[lane + 32 * i] * tp[lane + 32 * i];
    #pragma unroll
    for (int o = 16; o; o >>= 1) acc += __shfl_xor_sync(0xffffffffu, acc, o);
    int a = mask_at(att, b * L2_ + L_ + t, mode);
    int d = mask_at(dtm, b * L2_ + L_ + t, mode);
    float tgt = (a && !d) ? 1.f : 0.f;
    float el = acc;
    float bce = fmaxf(el, 0.f) + log1pf(expf(-fabsf(el))) - el * tgt;
    __shared__ float sS[8], sC[8];
    if (lane == 0) { sS[warp] = a ? bce : 0.f; sC[warp] = (float)a; }
    __syncthreads();
    if (threadIdx.x == 0) {
        float s = 0.f, c = 0.f;
        #pragma unroll
        for (int i = 0; i < 8; i++) { s += sS[i]; c += sC[i]; }
        g_emp_S[blockIdx.x] = s; g_emp_C[blockIdx.x] = c;
    }
}

// ======================= wmma tf32 GEMM + masked exp-sum (pipelined) =======================
// 128x128 tile per block; 8 warps in 4x2; warp tile 32x64 as 2x4 m16n16k8 frags.
// cp.async double-buffered mainloop, k-chunk 16; tf32 conversion at fragment level.
// den[b,l] partial over this block's 128 t-columns -> g_den_part[row][tt]
__global__ void __launch_bounds__(256, 2) k_gemm(const float* __restrict__ box,
                                                 const float* __restrict__ tag,
                                                 const void* __restrict__ dtm) {
    // [stage][A=0/B=1][row][col(pad 20)] ; epilogue scratch aliased on top after mainloop
    __shared__ alignas(32) float sbuf[2][2][128][20];
    __shared__ float red[128][2];
    __shared__ unsigned char sdtm[128];

    int mode = g_mask_mode;
    int b = blockIdx.z, lt = blockIdx.y, tt = blockIdx.x;
    int tid = threadIdx.x;
    int wid = tid >> 5, lane = tid & 31;
    int wm = wid >> 1, wn = wid & 1;     // 4 x 2 warp grid

    if (tid < 128) sdtm[tid] = (unsigned char)mask_at(dtm, b * L2_ + L_ + tt * 128 + tid, mode);

    const float* A  = box + (size_t)(b * L_ + lt * 128) * D_;
    const float* Bt = tag + (size_t)(b * L_ + tt * 128) * D_;

    wmma::fragment<wmma::accumulator, 16, 16, 8, float> acc[2][4];
    #pragma unroll
    for (int mi = 0; mi < 2; mi++)
        #pragma unroll
        for (int ni = 0; ni < 4; ni++)
            wmma::fill_fragment(acc[mi][ni], 0.0f);

    // stage prefetch: 128 rows x 16 cols for A and B = 2x512 float4; 4 per thread
    auto prefetch = [&](int s, int kc) {
        #pragma unroll
        for (int it = 0; it < 2; it++) {
            int a = tid + it * 256;              // 0..511
            int r = a >> 2, c4 = (a & 3) * 4;
            __pipeline_memcpy_async(&sbuf[s][0][r][c4], A + (size_t)r * D_ + kc + c4, 16);
        }
        #pragma unroll
        for (int it = 0; it < 2; it++) {
            int a = tid + it * 256;
            int r = a >> 2, c4 = (a & 3) * 4;
            __pipeline_memcpy_async(&sbuf[s][1][r][c4], Bt + (size_t)r * D_ + kc + c4, 16);
        }
        __pipeline_commit();
    };

    prefetch(0, 0);
    const int NIT = D_ / KCH;            // 32
    for (int i = 0; i < NIT; i++) {
        if (i + 1 < NIT) prefetch((i + 1) & 1, (i + 1) * KCH);
        __pipeline_wait_prior((i + 1 < NIT) ? 1 : 0);
        __syncthreads();
        int s = i & 1;
        #pragma unroll
        for (int kk = 0; kk < KCH; kk += 8) {
            wmma::fragment<wmma::matrix_a, 16, 16, 8, wmma::precision::tf32, wmma::row_major> af[2];
            #pragma unroll
            for (int mi = 0; mi < 2; mi++) {
                wmma::load_matrix_sync(af[mi], &sbuf[s][0][wm * 32 + mi * 16][kk], 20);
                #pragma unroll
                for (int e = 0; e < af[mi].num_elements; e++)
                    af[mi].x[e] = wmma::__float_to_tf32(af[mi].x[e]);
            }
            wmma::fragment<wmma::matrix_b, 16, 16, 8, wmma::precision::tf32, wmma::col_major> bf[4];
            #pragma unroll
            for (int ni = 0; ni < 4; ni++) {
                wmma::load_matrix_sync(bf[ni], &sbuf[s][1][wn * 64 + ni * 16][kk], 20);
                #pragma unroll
                for (int e = 0; e < bf[ni].num_elements; e++)
                    bf[ni].x[e] = wmma::__float_to_tf32(bf[ni].x[e]);
            }
            #pragma unroll
            for (int mi = 0; mi < 2; mi++)
                #pragma unroll
                for (int ni = 0; ni < 4; ni++)
                    wmma::mma_sync(acc[mi][ni], af[mi], bf[ni], acc[mi][ni]);
        }
        __syncthreads();
    }

    // epilogue: masked exp + row reduce; per-warp scratch aliased onto sbuf
    // (mainloop done; trailing __syncthreads above protects the reuse)
    float* scr = &sbuf[0][0][0][0] + wid * (16 * 20);   // 1280B/warp slice, 32B-aligned
    int r = lane & 15, h = lane >> 4;    // row within frag, column half
    #pragma unroll
    for (int mi = 0; mi < 2; mi++) {
        float rowsum = 0.f;
        #pragma unroll
        for (int ni = 0; ni < 4; ni++) {
            wmma::store_matrix_sync(scr, acc[mi][ni], 20, wmma::mem_row_major);
            __syncwarp();
            float s = 0.f;
            #pragma unroll
            for (int c = 0; c < 8; c++) {
                int col = h * 8 + c;
                int gc = wn * 64 + ni * 16 + col;
                if (sdtm[gc]) s += __expf(scr[r * 20 + col] * INV_TEMP);
            }
            rowsum += s;
            __syncwarp();
        }
        rowsum += __shfl_xor_sync(0xffffffffu, rowsum, 16);
        if (h == 0) red[wm * 32 + mi * 16 + r][wn] = rowsum;
    }
    __syncthreads();
    if (tid < 128) {
        float s = red[tid][0] + red[tid][1];
        g_den_part[(size_t)(b * L_ + lt * 128 + tid) * 8 + tt] = s;
    }
}

// ======================= pointer loss (targets + combine) =======================
__global__ void __launch_bounds__(256) k_ptr(const float* __restrict__ box,
                                             const float* __restrict__ tag,
                                             const int* __restrict__ bidx,
                                             const void* __restrict__ dtm) {
    int mode = g_mask_mode;
    int warp = threadIdx.x >> 5, lane = threadIdx.x & 31;
    int gw = blockIdx.x * 8 + warp;          // gw = b*L + l
    int b = gw >> 10;
    float dv = (lane < 8) ? g_den_part[(size_t)gw * 8 + lane] : 0.f;
    #pragma unroll
    for (int o = 16; o; o >>= 1) dv += __shfl_xor_sync(0xffffffffu, dv, o);
    float logden = logf(dv + EPSF);
    const int* bi = bidx + (size_t)gw * K_;
    const float* brow = box + (size_t)gw * D_;
    float ts = 0.f, tc = 0.f;
    bool valid = true;
    for (int k = 0; k < K_; k++) {
        int idx = bi[k];
        if (idx < 0) valid = false;
        if (valid) {
            int rc = idx - L_;
            rc = rc < 0 ? 0 : (rc > L_ - 1 ? L_ - 1 : rc);
            if (mask_at(dtm, b * L2_ + L_ + rc, mode)) {
                const float* trow = tag + (size_t)(b * L_ + rc) * D_;
                float a = 0.f;
                #pragma unroll
                for (int i = 0; i < 16; i++) a += brow[lane + 32 * i] * trow[lane + 32 * i];
                #pragma unroll
                for (int o = 16; o; o >>= 1) a += __shfl_xor_sync(0xffffffffu, a, o);
                ts += logden - a * INV_TEMP;
                tc += 1.f;
            }
        }
    }
    __shared__ float sS[8], sC[8];
    if (lane == 0) { sS[warp] = ts; sC[warp] = tc; }
    __syncthreads();
    if (threadIdx.x == 0) {
        float s = 0.f, c = 0.f;
        #pragma unroll
        for (int i = 0; i < 8; i++) { s += sS[i]; c += sC[i]; }
        g_ptr_S[blockIdx.x] = s; g_ptr_C[blockIdx.x] = c;
    }
}

// ======================= span contrastive =======================
__global__ void __launch_bounds__(256) k_contr(const float* __restrict__ sim,
                                               const float* __restrict__ coef, int slot) {
    int bi = blockIdx.x;
    int i = bi & 1023;
    int tid = threadIdx.x;
    const float4 sv = *(const float4*)(sim  + (size_t)bi * L_ + tid * 4);
    const float4 cv = *(const float4*)(coef + (size_t)bi * L_ + tid * 4);
    float s[4] = { sv.x * INV_TEMP, sv.y * INV_TEMP, sv.z * INV_TEMP, sv.w * INV_TEMP };
    float c[4] = { cv.x, cv.y, cv.z, cv.w };
    float m = fmaxf(fmaxf(s[0], s[1]), fmaxf(s[2], s[3]));
    #pragma unroll
    for (int o = 16; o; o >>= 1) m = fmaxf(m, __shfl_xor_sync(0xffffffffu, m, o));
    __shared__ float smax[8];
    __shared__ float sacc[8][3];
    __shared__ float sdiag;
    if ((tid & 31) == 0) smax[tid >> 5] = m;
    __syncthreads();
    if (tid == 0) {
        float mm = smax[0];
        #pragma unroll
        for (int w = 1; w < 8; w++) mm = fmaxf(mm, smax[w]);
        smax[0] = mm;
    }
    __syncthreads();
    m = smax[0];
    float es = 0.f, W = 0.f, WS = 0.f;
    #pragma unroll
    for (int q = 0; q < 4; q++) {
        float sq = s[q] - m;
        float e = expf(sq);
        es += e;
        if (tid * 4 + q == i) sdiag = e;
        float w = c[q] > 0.f ? c[q] : 0.f;
        W += w; WS += w * sq;
    }
    #pragma unroll
    for (int o = 16; o; o >>= 1) {
        es += __shfl_xor_sync(0xffffffffu, es, o);
        W  += __shfl_xor_sync(0xffffffffu, W, o);
        WS += __shfl_xor_sync(0xffffffffu, WS, o);
    }
    if ((tid & 31) == 0) { sacc[tid >> 5][0] = es; sacc[tid >> 5][1] = W; sacc[tid >> 5][2] = WS; }
    __syncthreads();
    if (tid == 0) {
        float E = 0.f, Wt = 0.f, WSt = 0.f;
        #pragma unroll
        for (int w = 0; w < 8; w++) { E += sacc[w][0]; Wt += sacc[w][1]; WSt += sacc[w][2]; }
        float den = E - sdiag;
        float logden = logf(den + EPSF);
        float haspos = Wt > 0.f ? 1.f : 0.f;
        float loss = (logden * Wt - WSt) / (Wt + EPSF);
        g_con_L[slot * (B_ * L_) + bi] = haspos * loss;
        g_con_P[slot * (B_ * L_) + bi] = haspos;
    }
}

// ======================= final deterministic combine =======================
__device__ float blk_sum(const float* p, int n, volatile float* sh) {
    float a = 0.f;
    for (int i = threadIdx.x; i < n; i += 256) a += p[i];
    #pragma unroll
    for (int o = 16; o; o >>= 1) a += __shfl_xor_sync(0xffffffffu, a, o);
    __syncthreads();
    if ((threadIdx.x & 31) == 0) sh[threadIdx.x >> 5] = a;
    __syncthreads();
    if (threadIdx.x == 0) {
        float r = 0.f;
        for (int w = 0; w < 8; w++) r += sh[w];
        sh[8] = r;
    }
    __syncthreads();
    float r = sh[8];
    __syncthreads();
    return r;
}

__global__ void __launch_bounds__(256) k_final(float* __restrict__ out) {
    __shared__ float sh[16];
    float clsS = blk_sum(g_cls_S, 1024, sh);
    float clsC = blk_sum(g_cls_C, 1024, sh);
    float cls = clsS / fmaxf(clsC, 1.f);

    float emp = 0.f;
    for (int b = 0; b < B_; b++) {
        float S = blk_sum(g_emp_S + b * 128, 128, sh);
        float C = blk_sum(g_emp_C + b * 128, 128, sh);
        emp += S / fmaxf(C, 1.f);
    }
    emp *= (1.f / B_);

    float ptrS = blk_sum(g_ptr_S, 1024, sh);
    float ptrC = blk_sum(g_ptr_C, 1024, sh);
    float ptr = (ptrC > 0.f) ? ptrS / fmaxf(ptrC, 1.f) : 0.f;

    float rL = blk_sum(g_con_L, B_ * L_, sh);
    float rP = blk_sum(g_con_P, B_ * L_, sh);
    float row = (rP > 0.f) ? rL / fmaxf(rP, 1.f) : 0.f;

    float cL = blk_sum(g_con_L + B_ * L_, B_ * L_, sh);
    float cP = blk_sum(g_con_P + B_ * L_, B_ * L_, sh);
    float col = (cP > 0.f) ? cL / fmaxf(cP, 1.f) : 0.f;

    if (threadIdx.x == 0) {
        out[1] = cls; out[2] = ptr; out[3] = emp; out[4] = row; out[5] = col;
        out[0] = cls + ptr + emp + 0.5f * row + 0.5f * col;
    }
}

// ======================= launch =======================
extern "C" void kernel_launch(void* const* d_in, const int* in_sizes, int n_in,
                              void* d_out, int out_size) {
    (void)in_sizes; (void)n_in; (void)out_size;
    const int*           tok  = (const int*)d_in[0];            // token_ids (B,L)
    const int*           bidx = (const int*)d_in[1];            // box_indices (B,L,K)
    const void*          dtm  = d_in[2];                        // data_tag_mask (B,2L)
    const void*          att  = d_in[3];                        // attention_mask (B,2L)
    const float*         tlog = (const float*)d_in[4];          // tag_logits (B,L,V)
    const float*         boxp = (const float*)d_in[5];          // box_proj (B,L,D)
    const float*         tagp = (const float*)d_in[6];          // tag_proj (B,L,D)
    const float*         empp = (const float*)d_in[7];          // empty_proj (B,1,D)
    const float*         rsim = (const float*)d_in[8];
    const float*         csim = (const float*)d_in[9];
    const float*         rco  = (const float*)d_in[10];
    const float*         cco  = (const float*)d_in[11];
    float* out = (float*)d_out;

    k_detect<<<1, 1>>>((const unsigned int*)att);
    k_cls<<<1024, 256>>>(tlog, tok);
    k_empty<<<1024, 256>>>(tagp, empp, att, dtm);
    dim3 gg(8, 8, B_);
    k_gemm<<<gg, 256>>>(boxp, tagp, dtm);
    k_ptr<<<1024, 256>>>(boxp, tagp, bidx, dtm);
    k_contr<<<B_ * L_, 256>>>(rsim, rco, 0);
    k_contr<<<B_ * L_, 256>>>(csim, cco, 1);
    k_final<<<1, 256>>>(out);
}